// round 3
// baseline (speedup 1.0000x reference)
#include <cuda_runtime.h>
#include <math.h>

// Problem constants (from reference setup_inputs):
//   x:      [B=256, H=64, W=64, D=256]  -> B x K floats, K = 64*64*256 = 1048576
//   memory: [E=8,  HW=4096, D=256]      -> E x K floats
#define BN   256
#define EN   8
#define KN   1048576
#define K4N  (KN / 4)
#define CK   1024            // chunk size in floats (pass-1 tile along K)
#define CK4  (CK / 4)
#define NCH  (KN / CK)       // 1024 chunks
#define BT   32              // b-samples per block tile in pass 1
#define NBT  (BN / BT)       // 8

typedef unsigned long long ull;

// Scratch (device globals -- no allocation allowed).
// g_dotp layout: [b][j][c] with j in 0..7 = dot(x_b, m_j) partial, j==8 = ||x_b||^2 partial
__device__ float g_dotp[(size_t)BN * 9 * NCH];   // 9.4 MB
__device__ float g_mpart[EN * NCH];              // ||m_e||^2 partials per chunk
__device__ int   g_experts[BN];
__device__ int   g_order[BN];
__device__ int   g_offs[EN + 1];
__device__ float g_ka[EN];
__device__ float g_kb[EN];

__device__ __forceinline__ float warp_sum(float v) {
    #pragma unroll
    for (int o = 16; o; o >>= 1)
        v += __shfl_xor_sync(0xffffffffu, v, o);
    return v;
}

// Packed fp32x2 FMA (Blackwell FFMA2) -- 2 IEEE fp32 FMAs per instruction,
// same fma pipe slot as scalar FFMA. ptxas never auto-fuses this; PTX only.
__device__ __forceinline__ ull fma2(ull a, ull b, ull c) {
    ull d;
    asm("fma.rn.f32x2 %0, %1, %2, %3;" : "=l"(d) : "l"(a), "l"(b), "l"(c));
    return d;
}
__device__ __forceinline__ float2 unpk(ull v) {
    float2 r;
    asm("mov.b64 {%0, %1}, %2;" : "=f"(r.x), "=f"(r.y) : "l"(v));
    return r;
}

// ---------------------------------------------------------------------------
// Pass 1: per-(b, chunk) partial dots + norms.
// Register-blocked over 4 b's per warp; inner product done with packed f32x2
// FMAs (FFMA2) -> half the fma-pipe instructions of scalar FFMA. Loads are
// ulonglong2 (LDG.128 / LDS.128) so packed floats land in 64-bit reg pairs.
// ---------------------------------------------------------------------------
__global__ void __launch_bounds__(256) k_dots(const float* __restrict__ x,
                                              const float* __restrict__ mem)
{
    __shared__ ulonglong2 sm[EN * CK4];   // 8 * 256 * 16B = 32 KB

    const int c   = blockIdx.x;       // chunk index
    const int bt  = blockIdx.y;       // b tile index
    const int tid = threadIdx.x;
    const int w   = tid >> 5;
    const int l   = tid & 31;

    // Stage m chunk: 2048 16B slots / 256 threads = 8 each
    const ulonglong2* m4 = (const ulonglong2*)mem;
    #pragma unroll
    for (int i = 0; i < 8; ++i) {
        int slot = tid + 256 * i;
        int e  = slot >> 8;           // /256
        int q  = slot & 255;
        sm[slot] = m4[(size_t)e * K4N + (size_t)c * CK4 + q];
    }
    __syncthreads();

    // One tile of blocks also produces ||m_e||^2 chunk partials (warp w == expert w)
    if (bt == 0) {
        ull s2 = 0ull;
        #pragma unroll
        for (int g = 0; g < 8; ++g) {
            ulonglong2 f = sm[w * CK4 + g * 32 + l];
            s2 = fma2(f.x, f.x, s2);
            s2 = fma2(f.y, f.y, s2);
        }
        float2 p = unpk(s2);
        float s = warp_sum(p.x + p.y);
        if (l == 0) g_mpart[w * NCH + c] = s;
    }

    const ulonglong2* x4 = (const ulonglong2*)x;

    // Warp w handles b's: bt*32 + {0,1,2,3}*8 + w, all four concurrently.
    ull d[4][EN];     // packed f32x2 accumulators
    ull nx[4];
    #pragma unroll
    for (int i = 0; i < 4; ++i) {
        nx[i] = 0ull;
        #pragma unroll
        for (int e = 0; e < EN; ++e) d[i][e] = 0ull;
    }

    const ulonglong2* xp0 = x4 + (size_t)(bt * BT + 0 * 8 + w) * K4N + (size_t)c * CK4;
    const ulonglong2* xp1 = x4 + (size_t)(bt * BT + 1 * 8 + w) * K4N + (size_t)c * CK4;
    const ulonglong2* xp2 = x4 + (size_t)(bt * BT + 2 * 8 + w) * K4N + (size_t)c * CK4;
    const ulonglong2* xp3 = x4 + (size_t)(bt * BT + 3 * 8 + w) * K4N + (size_t)c * CK4;

    #pragma unroll
    for (int g = 0; g < 8; ++g) {
        const int o = g * 32 + l;
        ulonglong2 xv[4];
        xv[0] = xp0[o];
        xv[1] = xp1[o];
        xv[2] = xp2[o];
        xv[3] = xp3[o];

        #pragma unroll
        for (int i = 0; i < 4; ++i) {
            nx[i] = fma2(xv[i].x, xv[i].x, nx[i]);
            nx[i] = fma2(xv[i].y, xv[i].y, nx[i]);
        }

        #pragma unroll
        for (int e = 0; e < EN; ++e) {
            const ulonglong2 mv = sm[e * CK4 + o];   // ONE smem load, used 4x
            #pragma unroll
            for (int i = 0; i < 4; ++i) {
                d[i][e] = fma2(xv[i].x, mv.x, d[i][e]);
                d[i][e] = fma2(xv[i].y, mv.y, d[i][e]);
            }
        }
    }

    #pragma unroll
    for (int i = 0; i < 4; ++i) {
        const int b = bt * BT + i * 8 + w;
        float* dst = g_dotp + (size_t)b * 9 * NCH;
        #pragma unroll
        for (int e = 0; e < EN; ++e) {
            float2 p = unpk(d[i][e]);
            float v = warp_sum(p.x + p.y);
            if (l == 0) dst[e * NCH + c] = v;
        }
        float2 p = unpk(nx[i]);
        float v = warp_sum(p.x + p.y);
        if (l == 0) dst[8 * NCH + c] = v;
    }
}

// ---------------------------------------------------------------------------
// Pass 2: reduce chunk partials per b, cosine sim, argmax (first-max rule).
// Deterministic fixed-order reductions.
// ---------------------------------------------------------------------------
__global__ void __launch_bounds__(256) k_argmax(float* __restrict__ outExp)
{
    const int b   = blockIdx.x;
    const int tid = threadIdx.x;
    const int w   = tid >> 5;
    const int l   = tid & 31;

    __shared__ float sdot[EN];
    __shared__ float smn[EN];
    __shared__ float snx;

    // dot[e = w]
    {
        const float* p = g_dotp + (size_t)b * 9 * NCH + (size_t)w * NCH;
        float v = 0.f;
        #pragma unroll
        for (int g = 0; g < NCH / 32; ++g) v += p[g * 32 + l];
        v = warp_sum(v);
        if (l == 0) sdot[w] = v;
    }
    // ||x_b||^2 (warp 0, second pass)
    if (w == 0) {
        const float* p = g_dotp + (size_t)b * 9 * NCH + (size_t)8 * NCH;
        float v = 0.f;
        #pragma unroll
        for (int g = 0; g < NCH / 32; ++g) v += p[g * 32 + l];
        v = warp_sum(v);
        if (l == 0) snx = v;
    }
    // ||m_e||^2 (redundant per block, trivial traffic)
    {
        const float* p = g_mpart + (size_t)w * NCH;
        float v = 0.f;
        #pragma unroll
        for (int g = 0; g < NCH / 32; ++g) v += p[g * 32 + l];
        v = warp_sum(v);
        if (l == 0) smn[w] = v;
    }
    __syncthreads();

    if (tid == 0) {
        float nx = sqrtf(snx);
        float best = -3.4e38f;
        int   bi   = 0;
        #pragma unroll
        for (int e = 0; e < EN; ++e) {
            float denom = fmaxf(nx * sqrtf(smn[e]), 1e-8f);
            float s = sdot[e] / denom;
            if (s > best) { best = s; bi = e; }   // strict > == first-max (jnp.argmax)
        }
        g_experts[b] = bi;
        if (outExp) outExp[b] = (float)bi;
    }
}

// ---------------------------------------------------------------------------
// Counting sort of b by expert (stable -> deterministic), plus update coeffs:
// out = ka*m + kb*sum_x, ka = count>0 ? 0.5 : 1, kb = count>0 ? 0.5/count : 0.
// ---------------------------------------------------------------------------
__global__ void k_sort()
{
    __shared__ int s_exp[BN];
    const int tid = threadIdx.x;
    s_exp[tid] = g_experts[tid];
    __syncthreads();

    if (tid == 0) {
        int counts[EN];
        #pragma unroll
        for (int e = 0; e < EN; ++e) counts[e] = 0;
        for (int b = 0; b < BN; ++b) counts[s_exp[b]]++;

        int pos[EN];
        int off = 0;
        #pragma unroll
        for (int e = 0; e < EN; ++e) {
            g_offs[e] = off;
            pos[e] = off;
            off += counts[e];
        }
        g_offs[EN] = off;

        for (int b = 0; b < BN; ++b) {
            int e = s_exp[b];
            g_order[pos[e]++] = b;
        }
        #pragma unroll
        for (int e = 0; e < EN; ++e) {
            if (counts[e] > 0) { g_ka[e] = 0.5f; g_kb[e] = 0.5f / (float)counts[e]; }
            else               { g_ka[e] = 1.0f; g_kb[e] = 0.0f; }
        }
    }
}

// ---------------------------------------------------------------------------
// Pass 3: scatter-mean update. Each thread owns one float4 column j; loops the
// sorted b-list per expert (single register accumulator, x read exactly once).
// 86% DRAM already -- near roofline, unchanged.
// ---------------------------------------------------------------------------
__global__ void __launch_bounds__(256) k_update(const float* __restrict__ x,
                                                const float* __restrict__ mem,
                                                float* __restrict__ outMem)
{
    __shared__ int   s_order[BN];
    __shared__ int   s_offs[EN + 1];
    __shared__ float s_ka[EN];
    __shared__ float s_kb[EN];

    const int tid = threadIdx.x;
    s_order[tid] = g_order[tid];
    if (tid < EN + 1) s_offs[tid] = g_offs[tid];
    if (tid < EN)     { s_ka[tid] = g_ka[tid]; s_kb[tid] = g_kb[tid]; }
    __syncthreads();

    const size_t j4 = (size_t)blockIdx.x * 256 + tid;
    const float4* x4 = (const float4*)x;
    const float4* m4 = (const float4*)mem;
    float4*       o4 = (float4*)outMem;

    #pragma unroll 1
    for (int e = 0; e < EN; ++e) {
        float ax = 0.f, ay = 0.f, az = 0.f, aw = 0.f;
        const int lo = s_offs[e];
        const int hi = s_offs[e + 1];
        #pragma unroll 4
        for (int i = lo; i < hi; ++i) {
            int b = s_order[i];
            float4 f = x4[(size_t)b * K4N + j4];
            ax += f.x; ay += f.y; az += f.z; aw += f.w;
        }
        const float ka = s_ka[e];
        const float kb = s_kb[e];
        float4 mv = m4[(size_t)e * K4N + j4];
        float4 ov;
        ov.x = ka * mv.x + kb * ax;
        ov.y = ka * mv.y + kb * ay;
        ov.z = ka * mv.z + kb * az;
        ov.w = ka * mv.w + kb * aw;
        o4[(size_t)e * K4N + j4] = ov;
    }
}

// ---------------------------------------------------------------------------
extern "C" void kernel_launch(void* const* d_in, const int* in_sizes, int n_in,
                              void* d_out, int out_size)
{
    const float* x   = (const float*)d_in[0];
    const float* mem = (const float*)d_in[1];
    float* out = (float*)d_out;

    const long memElems = (long)EN * KN;          // 8388608
    float* outExp = nullptr;
    float* outMem = nullptr;
    if ((long)out_size == memElems + BN) {        // concat: experts then new_memory
        outExp = out;
        outMem = out + BN;
    } else if ((long)out_size == memElems) {      // new_memory only
        outMem = out;
    } else {                                      // experts only (fallback)
        outExp = out;
    }

    dim3 g1(NCH, NBT);
    k_dots<<<g1, 256>>>(x, mem);
    k_argmax<<<BN, 256>>>(outExp);
    k_sort<<<1, 256>>>();
    if (outMem) k_update<<<K4N / 256, 256>>>(x, mem, outMem);
}

// round 4
// speedup vs baseline: 1.4082x; 1.4082x over previous
#include <cuda_runtime.h>
#include <math.h>

// x: [B=256, K=1048576]; memory: [E=8, K]
#define BN   256
#define EN   8
#define KN   1048576
#define K4N  (KN / 4)
#define CK   512             // chunk size in floats (k per block)
#define CK4  (CK / 4)        // 128
#define NCH  (KN / CK)       // 2048 chunks
#define KS   32              // k-slice staged in smem per warp step
#define NSL  (CK / KS)       // 16 slices per chunk
#define XSTR 36              // x_s row stride (floats): 36 % 32 == 4 -> conflict-free A loads
#define MSTR 516             // m_s row stride (floats): 516 % 32 == 4 -> conflict-free B loads

// Scratch (device globals -- no allocation allowed).
// g_dotp layout: [b][j][c], j=0..7 dot partial per expert, j=8 ||x||^2 partial
__device__ float g_dotp[(size_t)BN * 9 * NCH];   // 18.9 MB
__device__ float g_mpart[EN * NCH];
__device__ int   g_experts[BN];
__device__ int   g_order[BN];
__device__ int   g_offs[EN + 1];
__device__ float g_ka[EN];
__device__ float g_kb[EN];

__device__ __forceinline__ float warp_sum(float v) {
    #pragma unroll
    for (int o = 16; o; o >>= 1)
        v += __shfl_xor_sync(0xffffffffu, v, o);
    return v;
}

// tf32 m16n8k8 MMA: D += A(16x8) * B(8x8). fp32 inputs reinterpreted as tf32
// (HW reads sign/exp/10-bit mantissa; truncation error ~1e-6 in sim units,
// only the argmax depends on it).
__device__ __forceinline__ void mma_tf32(float acc[4],
                                         float a0, float a1, float a2, float a3,
                                         float b0, float b1) {
    asm volatile(
        "mma.sync.aligned.m16n8k8.row.col.f32.tf32.tf32.f32 "
        "{%0,%1,%2,%3}, {%4,%5,%6,%7}, {%8,%9}, {%0,%1,%2,%3};\n"
        : "+f"(acc[0]), "+f"(acc[1]), "+f"(acc[2]), "+f"(acc[3])
        : "r"(__float_as_uint(a0)), "r"(__float_as_uint(a1)),
          "r"(__float_as_uint(a2)), "r"(__float_as_uint(a3)),
          "r"(__float_as_uint(b0)), "r"(__float_as_uint(b1)));
}

// ---------------------------------------------------------------------------
// Pass 1: tensor-core dot partials + exact fp32 norms.
// Block: 8 warps, 128 b-rows (16 per warp), one k-chunk of 512.
// m chunk staged in smem (shared by all warps); x staged per-warp in 32-float
// slices with register prefetch. All LDS/STS patterns are bank-conflict-free.
// ---------------------------------------------------------------------------
__global__ void __launch_bounds__(256) k_dots(const float* __restrict__ x,
                                              const float* __restrict__ mem)
{
    __shared__ float m_s[EN * MSTR];          // 16.5 KB
    __shared__ float x_s[8][16 * XSTR];       // 18.4 KB (per-warp 16 x 36)

    const int c   = blockIdx.x;               // chunk
    const int bt  = blockIdx.y;               // b tile (0..1), 128 b each
    const int tid = threadIdx.x;
    const int w   = tid >> 5;
    const int l   = tid & 31;
    const int g   = l >> 2;                   // 0..7  (mma groupID)
    const int tg  = l & 3;                    // 0..3  (mma thread-in-group)

    // ---- stage m chunk: 1024 float4 / 256 threads = 4 each (coalesced) ----
    const float4* m4 = (const float4*)mem;
    #pragma unroll
    for (int i = 0; i < 4; ++i) {
        int slot = tid + 256 * i;             // 0..1023
        int e = slot >> 7;                    // /128
        int q = slot & 127;
        float4 v = m4[(size_t)e * K4N + (size_t)c * CK4 + q];
        *(float4*)&m_s[e * MSTR + 4 * q] = v;
    }
    __syncthreads();

    // ---- ||m_e||^2 chunk partials (one b-tile only; warp w == expert w) ----
    if (bt == 0) {
        float s = 0.f;
        #pragma unroll
        for (int j = 0; j < 4; ++j) {
            float4 f = *(const float4*)&m_s[w * MSTR + 4 * (l + 32 * j)];
            s += f.x * f.x + f.y * f.y + f.z * f.z + f.w * f.w;
        }
        s = warp_sum(s);
        if (l == 0) g_mpart[w * NCH + c] = s;
    }

    // ---- main loop: warp owns rows b0row..b0row+15 ----
    const int b0row = bt * 128 + w * 16;
    const float4* x4 = (const float4*)x;

    // staging lane map: r0 = l>>3 (0..3), q = l&7 (0..7); rows r0+4i
    const int r0 = l >> 3;
    const int q  = l & 7;

    float accA[4] = {0.f, 0.f, 0.f, 0.f};
    float accB[4] = {0.f, 0.f, 0.f, 0.f};
    float n00 = 0.f, n01 = 0.f, n10 = 0.f, n11 = 0.f;

    // prefetch slice 0
    float4 pf[4];
    #pragma unroll
    for (int i = 0; i < 4; ++i)
        pf[i] = x4[(size_t)(b0row + r0 + 4 * i) * K4N + (size_t)c * CK4 + q];

    float* xw = &x_s[w][0];

    #pragma unroll 1
    for (int s = 0; s < NSL; ++s) {
        __syncwarp();                          // prior slice fully consumed
        #pragma unroll
        for (int i = 0; i < 4; ++i)
            *(float4*)&xw[(r0 + 4 * i) * XSTR + 4 * q] = pf[i];
        __syncwarp();                          // STS visible to warp

        if (s + 1 < NSL) {
            #pragma unroll
            for (int i = 0; i < 4; ++i)
                pf[i] = x4[(size_t)(b0row + r0 + 4 * i) * K4N
                           + (size_t)c * CK4 + (s + 1) * (KS / 4) + q];
        }

        const int cbase = s * KS;              // column base within chunk (for B)
        #pragma unroll
        for (int k8 = 0; k8 < KS / 8; ++k8) {
            const int k = k8 * 8;
            // A fragments (row-major 16x8): rows g and g+8, cols k+tg, k+4+tg
            float a0 = xw[g       * XSTR + k + tg];
            float a1 = xw[(g + 8) * XSTR + k + tg];
            float a2 = xw[g       * XSTR + k + 4 + tg];
            float a3 = xw[(g + 8) * XSTR + k + 4 + tg];
            // B fragments (col-major 8x8): B[k][n] = m[n][k]; n = g
            float b0 = m_s[g * MSTR + cbase + k + tg];
            float b1 = m_s[g * MSTR + cbase + k + 4 + tg];

            // exact fp32 norms (4 independent chains)
            n00 += a0 * a0;  n01 += a2 * a2;
            n10 += a1 * a1;  n11 += a3 * a3;

            if (k8 & 1) mma_tf32(accB, a0, a1, a2, a3, b0, b1);
            else        mma_tf32(accA, a0, a1, a2, a3, b0, b1);
        }
    }

    // ---- write dot partials: D[r][e], r = g / g+8, e = 2tg / 2tg+1 ----
    const float d0 = accA[0] + accB[0];
    const float d1 = accA[1] + accB[1];
    const float d2 = accA[2] + accB[2];
    const float d3 = accA[3] + accB[3];

    const size_t bl = (size_t)(b0row + g)     * 9 * NCH;
    const size_t bh = (size_t)(b0row + g + 8) * 9 * NCH;
    g_dotp[bl + (size_t)(2 * tg)     * NCH + c] = d0;
    g_dotp[bl + (size_t)(2 * tg + 1) * NCH + c] = d1;
    g_dotp[bh + (size_t)(2 * tg)     * NCH + c] = d2;
    g_dotp[bh + (size_t)(2 * tg + 1) * NCH + c] = d3;

    // ---- norms: reduce across the 4 lanes of each g-group ----
    float ng  = n00 + n01;   // row g
    float ng8 = n10 + n11;   // row g+8
    ng  += __shfl_xor_sync(0xffffffffu, ng, 1);
    ng  += __shfl_xor_sync(0xffffffffu, ng, 2);
    ng8 += __shfl_xor_sync(0xffffffffu, ng8, 1);
    ng8 += __shfl_xor_sync(0xffffffffu, ng8, 2);
    if (tg == 0) {
        g_dotp[bl + (size_t)8 * NCH + c] = ng;
        g_dotp[bh + (size_t)8 * NCH + c] = ng8;
    }
}

// ---------------------------------------------------------------------------
// Pass 2: reduce chunk partials, cosine sim, argmax (first-max rule).
// ---------------------------------------------------------------------------
__global__ void __launch_bounds__(256) k_argmax(float* __restrict__ outExp)
{
    const int b   = blockIdx.x;
    const int tid = threadIdx.x;
    const int w   = tid >> 5;
    const int l   = tid & 31;

    __shared__ float sdot[EN];
    __shared__ float smn[EN];
    __shared__ float snx;

    {
        const float* p = g_dotp + (size_t)b * 9 * NCH + (size_t)w * NCH;
        float v = 0.f;
        #pragma unroll
        for (int g = 0; g < NCH / 32; ++g) v += p[g * 32 + l];
        v = warp_sum(v);
        if (l == 0) sdot[w] = v;
    }
    if (w == 0) {
        const float* p = g_dotp + (size_t)b * 9 * NCH + (size_t)8 * NCH;
        float v = 0.f;
        #pragma unroll
        for (int g = 0; g < NCH / 32; ++g) v += p[g * 32 + l];
        v = warp_sum(v);
        if (l == 0) snx = v;
    }
    {
        const float* p = g_mpart + (size_t)w * NCH;
        float v = 0.f;
        #pragma unroll
        for (int g = 0; g < NCH / 32; ++g) v += p[g * 32 + l];
        v = warp_sum(v);
        if (l == 0) smn[w] = v;
    }
    __syncthreads();

    if (tid == 0) {
        float nx = sqrtf(snx);
        float best = -3.4e38f;
        int   bi   = 0;
        #pragma unroll
        for (int e = 0; e < EN; ++e) {
            float denom = fmaxf(nx * sqrtf(smn[e]), 1e-8f);
            float s = sdot[e] / denom;
            if (s > best) { best = s; bi = e; }   // strict > == first-max (jnp.argmax)
        }
        g_experts[b] = bi;
        if (outExp) outExp[b] = (float)bi;
    }
}

// ---------------------------------------------------------------------------
// Counting sort of b by expert (stable -> deterministic) + update coeffs.
// ---------------------------------------------------------------------------
__global__ void k_sort()
{
    __shared__ int s_exp[BN];
    const int tid = threadIdx.x;
    s_exp[tid] = g_experts[tid];
    __syncthreads();

    if (tid == 0) {
        int counts[EN];
        #pragma unroll
        for (int e = 0; e < EN; ++e) counts[e] = 0;
        for (int b = 0; b < BN; ++b) counts[s_exp[b]]++;

        int pos[EN];
        int off = 0;
        #pragma unroll
        for (int e = 0; e < EN; ++e) {
            g_offs[e] = off;
            pos[e] = off;
            off += counts[e];
        }
        g_offs[EN] = off;

        for (int b = 0; b < BN; ++b) {
            int e = s_exp[b];
            g_order[pos[e]++] = b;
        }
        #pragma unroll
        for (int e = 0; e < EN; ++e) {
            if (counts[e] > 0) { g_ka[e] = 0.5f; g_kb[e] = 0.5f / (float)counts[e]; }
            else               { g_ka[e] = 1.0f; g_kb[e] = 0.0f; }
        }
    }
}

// ---------------------------------------------------------------------------
// Pass 3: scatter-mean update. 86% DRAM -- near roofline, unchanged.
// ---------------------------------------------------------------------------
__global__ void __launch_bounds__(256) k_update(const float* __restrict__ x,
                                                const float* __restrict__ mem,
                                                float* __restrict__ outMem)
{
    __shared__ int   s_order[BN];
    __shared__ int   s_offs[EN + 1];
    __shared__ float s_ka[EN];
    __shared__ float s_kb[EN];

    const int tid = threadIdx.x;
    s_order[tid] = g_order[tid];
    if (tid < EN + 1) s_offs[tid] = g_offs[tid];
    if (tid < EN)     { s_ka[tid] = g_ka[tid]; s_kb[tid] = g_kb[tid]; }
    __syncthreads();

    const size_t j4 = (size_t)blockIdx.x * 256 + tid;
    const float4* x4 = (const float4*)x;
    const float4* m4 = (const float4*)mem;
    float4*       o4 = (float4*)outMem;

    #pragma unroll 1
    for (int e = 0; e < EN; ++e) {
        float ax = 0.f, ay = 0.f, az = 0.f, aw = 0.f;
        const int lo = s_offs[e];
        const int hi = s_offs[e + 1];
        #pragma unroll 4
        for (int i = lo; i < hi; ++i) {
            int b = s_order[i];
            float4 f = x4[(size_t)b * K4N + j4];
            ax += f.x; ay += f.y; az += f.z; aw += f.w;
        }
        const float ka = s_ka[e];
        const float kb = s_kb[e];
        float4 mv = m4[(size_t)e * K4N + j4];
        float4 ov;
        ov.x = ka * mv.x + kb * ax;
        ov.y = ka * mv.y + kb * ay;
        ov.z = ka * mv.z + kb * az;
        ov.w = ka * mv.w + kb * aw;
        o4[(size_t)e * K4N + j4] = ov;
    }
}

// ---------------------------------------------------------------------------
extern "C" void kernel_launch(void* const* d_in, const int* in_sizes, int n_in,
                              void* d_out, int out_size)
{
    const float* x   = (const float*)d_in[0];
    const float* mem = (const float*)d_in[1];
    float* out = (float*)d_out;

    const long memElems = (long)EN * KN;          // 8388608
    float* outExp = nullptr;
    float* outMem = nullptr;
    if ((long)out_size == memElems + BN) {        // concat: experts then new_memory
        outExp = out;
        outMem = out + BN;
    } else if ((long)out_size == memElems) {      // new_memory only
        outMem = out;
    } else {                                      // experts only (fallback)
        outExp = out;
    }

    dim3 g1(NCH, 2);
    k_dots<<<g1, 256>>>(x, mem);
    k_argmax<<<BN, 256>>>(outExp);
    k_sort<<<1, 256>>>();
    if (outMem) k_update<<<K4N / 256, 256>>>(x, mem, outMem);
}